// round 3
// baseline (speedup 1.0000x reference)
#include <cuda_runtime.h>
#include <cstdint>

// RBDispatcher: two-stage gather + concat, fully fused.
//   out[r]        = x[ idx_s1[ s1_to_s2[r] ] / TOP_K ]   for r in [0, N_S2)
//   out[N_S2 + r] = x[ idx_s1[r] / TOP_K ]               for r in [0, N_S1)
//
// NOTE: the reference declares int64 indices, but JAX without x64 demotes
// them to int32 — the device buffers ARE int32 (reading as int64 caused the
// round-1 illegal access).
//
// d_in order:
//   0: x            float32 [N_TOKENS * D_MODEL]
//   1: indices_s1   int32   [N_S1]
//   2: s1exp_to_s2  int32   [N_S2]
//   3: n_tokens     (scalar)
//   4: top_k        (scalar)

static constexpr int D_MODEL = 2048;
static constexpr int TOP_K   = 2;
static constexpr int VECS    = D_MODEL / 4;  // 512 float4 per row

__global__ __launch_bounds__(256, 8)
void rb_dispatch_kernel(const float4* __restrict__ x,
                        const int* __restrict__ idx_s1,
                        const int* __restrict__ s1_to_s2,
                        float4* __restrict__ out,
                        int n_s2)
{
    const int row = blockIdx.x;

    // Compose the gather index (uniform across the block; broadcast load).
    int expanded;
    if (row < n_s2) {
        expanded = idx_s1[s1_to_s2[row]];
    } else {
        expanded = idx_s1[row - n_s2];
    }
    const int src_row = expanded / TOP_K;

    const float4* __restrict__ src = x + (long long)src_row * VECS;
    float4* __restrict__ dst = out + (long long)row * VECS;

    // 512 float4 per row, 256 threads -> 2 per thread, fully coalesced.
    #pragma unroll
    for (int i = threadIdx.x; i < VECS; i += 256) {
        float4 v = __ldg(&src[i]);
        // Streaming store: evict-first so the 192 MiB output stream does not
        // flush x (64 MiB, L2-resident) out of L2.
        __stcs(&dst[i], v);
    }
}

extern "C" void kernel_launch(void* const* d_in, const int* in_sizes, int n_in,
                              void* d_out, int out_size)
{
    const float4* x        = (const float4*)d_in[0];
    const int*    idx_s1   = (const int*)d_in[1];
    const int*    s1_to_s2 = (const int*)d_in[2];

    const int n_s1 = in_sizes[1];        // 16384
    const int n_s2 = in_sizes[2];        // 8192
    const int n_out_rows = n_s1 + n_s2;  // 24576

    rb_dispatch_kernel<<<n_out_rows, 256>>>(
        x, idx_s1, s1_to_s2, (float4*)d_out, n_s2);
}

// round 4
// speedup vs baseline: 1.0120x; 1.0120x over previous
#include <cuda_runtime.h>
#include <cstdint>

// RBDispatcher: two-stage gather + concat, fully fused.
//   out[r]        = x[ idx_s1[ s1_to_s2[r] ] / TOP_K ]   for r in [0, N_S2)
//   out[N_S2 + r] = x[ idx_s1[r] / TOP_K ]               for r in [0, N_S1)
//
// Indices are int32 on device (JAX demotes int64 without x64 enabled).
//
// R4 change vs R3 baseline (42.6us, DRAM 64.9%): the R3 loop was
// LDG->STG->LDG->STG, leaving ~1 load (128B/warp) in flight -> MLP-bound at
// ~5 TB/s. Now each block copies 2 rows and each thread BATCHES 4 float4
// loads before any store -> 4x bytes in flight, targeting the DRAM write
// roofline (~201MB / 8TB/s ~ 25us).

static constexpr int D_MODEL = 2048;
static constexpr int TOP_K   = 2;
static constexpr int VECS    = D_MODEL / 4;   // 512 float4 per row
static constexpr int NT      = 256;           // threads per block
static constexpr int ROWS_PER_BLK = 2;

__global__ __launch_bounds__(NT, 8)
void rb_dispatch_kernel(const float4* __restrict__ x,
                        const int* __restrict__ idx_s1,
                        const int* __restrict__ s1_to_s2,
                        float4* __restrict__ out,
                        int n_s2)
{
    const int row0 = blockIdx.x * ROWS_PER_BLK;
    const int row1 = row0 + 1;

    // Compose gather indices (uniform loads, broadcast through L1).
    int e0 = (row0 < n_s2) ? idx_s1[s1_to_s2[row0]] : idx_s1[row0 - n_s2];
    int e1 = (row1 < n_s2) ? idx_s1[s1_to_s2[row1]] : idx_s1[row1 - n_s2];
    const int s0 = e0 / TOP_K;
    const int s1 = e1 / TOP_K;

    const float4* __restrict__ src0 = x + (long long)s0 * VECS;
    const float4* __restrict__ src1 = x + (long long)s1 * VECS;
    float4* __restrict__ dst0 = out + (long long)row0 * VECS;
    float4* __restrict__ dst1 = out + (long long)row1 * VECS;

    const int t = threadIdx.x;

    // Batch ALL loads first (4 independent LDG.128 in flight per thread),
    // then all stores. 512 vec/row, 256 threads -> 2 vec/thread/row.
    float4 a0 = __ldg(&src0[t]);
    float4 a1 = __ldg(&src0[t + NT]);
    float4 b0 = __ldg(&src1[t]);
    float4 b1 = __ldg(&src1[t + NT]);

    // Streaming stores: evict-first so the 192 MiB output stream does not
    // flush x (64 MiB, L2-resident) out of L2 -> reads stay ~91% L2-hit.
    __stcs(&dst0[t],      a0);
    __stcs(&dst0[t + NT], a1);
    __stcs(&dst1[t],      b0);
    __stcs(&dst1[t + NT], b1);
}

extern "C" void kernel_launch(void* const* d_in, const int* in_sizes, int n_in,
                              void* d_out, int out_size)
{
    const float4* x        = (const float4*)d_in[0];
    const int*    idx_s1   = (const int*)d_in[1];
    const int*    s1_to_s2 = (const int*)d_in[2];

    const int n_s1 = in_sizes[1];        // 16384
    const int n_s2 = in_sizes[2];        // 8192
    const int n_out_rows = n_s1 + n_s2;  // 24576 (even)

    rb_dispatch_kernel<<<n_out_rows / ROWS_PER_BLK, NT>>>(
        x, idx_s1, s1_to_s2, (float4*)d_out, n_s2);
}